// round 1
// baseline (speedup 1.0000x reference)
#include <cuda_runtime.h>
#include <cuda_bf16.h>

#define NBX 512
#define NBY 512
#define KK  5
#define BINF 1.0f
#define TARGET_AREA 0.9f   // TARGET_DENSITY * BIN * BIN

// Scratch density map (device global; no cudaMalloc allowed)
__device__ float g_density[NBX * NBY];

// ---------------------------------------------------------------------------
// Kernel 1: init density map from initial_density_map, zero the output scalar
// ---------------------------------------------------------------------------
__global__ void init_kernel(const float* __restrict__ initial, float* __restrict__ out) {
    int i = blockIdx.x * blockDim.x + threadIdx.x;
    if (i < NBX * NBY) g_density[i] = initial[i];
    if (i == 0) out[0] = 0.0f;
}

// ---------------------------------------------------------------------------
// Kernel 2: per-node 5x5 separable bell-potential scatter
// ---------------------------------------------------------------------------
__global__ void __launch_bounds__(256) scatter_kernel(
    const float* __restrict__ pos,   // [2N]: x then y
    const float* __restrict__ sxs,
    const float* __restrict__ sys,
    const float* __restrict__ axs,
    const float* __restrict__ bxs,
    const float* __restrict__ cxs,
    const float* __restrict__ ays,
    const float* __restrict__ bys,
    const float* __restrict__ cys,
    int n)
{
    int i = blockIdx.x * blockDim.x + threadIdx.x;
    if (i >= n) return;

    float x  = pos[i];
    float y  = pos[n + i];
    float sx = sxs[i];
    float sy = sys[i];
    float ax = axs[i], bx = bxs[i], cx = cxs[i];
    float ay = ays[i], by = bys[i], cy = cys[i];

    // ----- x axis -----
    float cxr = x + 0.5f * sx;                 // node center
    int sx0 = (int)floorf(x - 2.0f * BINF);    // (x - 2*BIN - XL)/BIN, XL=0, BIN=1
    sx0 = min(max(sx0, 0), NBX - KK);
    float p1x = 0.5f * sx + BINF;
    float p2x = 0.5f * sx + 2.0f * BINF;
    float cbx = cx * bx;

    float px[KK];
#pragma unroll
    for (int k = 0; k < KK; k++) {
        float bc = ((float)(sx0 + k) + 0.5f) * BINF;   // bin center, exact
        float d  = fabsf(cxr - bc);
        float pot;
        if (d < p1x) {
            pot = cx * (1.0f - ax * d * d);
        } else if (d < p2x) {
            float t = d - p2x;
            pot = cbx * t * t;
        } else {
            pot = 0.0f;
        }
        px[k] = pot;
    }

    // ----- y axis -----
    float cyr = y + 0.5f * sy;
    int sy0 = (int)floorf(y - 2.0f * BINF);
    sy0 = min(max(sy0, 0), NBY - KK);
    float p1y = 0.5f * sy + BINF;
    float p2y = 0.5f * sy + 2.0f * BINF;
    float cby = cy * by;

    float py[KK];
#pragma unroll
    for (int k = 0; k < KK; k++) {
        float bc = ((float)(sy0 + k) + 0.5f) * BINF;
        float d  = fabsf(cyr - bc);
        float pot;
        if (d < p1y) {
            pot = cy * (1.0f - ay * d * d);
        } else if (d < p2y) {
            float t = d - p2y;
            pot = cby * t * t;
        } else {
            pot = 0.0f;
        }
        py[k] = pot;
    }

    // ----- 5x5 scatter -----
#pragma unroll
    for (int kx = 0; kx < KK; kx++) {
        float vx = px[kx];
        float* row = &g_density[(sx0 + kx) * NBY + sy0];
#pragma unroll
        for (int ky = 0; ky < KK; ky++) {
            atomicAdd(&row[ky], vx * py[ky]);
        }
    }
}

// ---------------------------------------------------------------------------
// Kernel 3: cost = sum((density - target)^2)
// ---------------------------------------------------------------------------
__global__ void __launch_bounds__(256) reduce_kernel(float* __restrict__ out) {
    __shared__ float sdata[256];
    int tid = threadIdx.x;
    float acc = 0.0f;
    for (int i = blockIdx.x * blockDim.x + tid; i < NBX * NBY;
         i += gridDim.x * blockDim.x) {
        float d = g_density[i] - TARGET_AREA;
        acc += d * d;
    }
    // warp reduce
#pragma unroll
    for (int off = 16; off > 0; off >>= 1)
        acc += __shfl_xor_sync(0xFFFFFFFF, acc, off);
    if ((tid & 31) == 0) sdata[tid >> 5] = acc;
    __syncthreads();
    if (tid < 8) {
        float v = sdata[tid];
#pragma unroll
        for (int off = 4; off > 0; off >>= 1)
            v += __shfl_xor_sync(0xFF, v, off);
        if (tid == 0) atomicAdd(out, v);
    }
}

// ---------------------------------------------------------------------------
extern "C" void kernel_launch(void* const* d_in, const int* in_sizes, int n_in,
                              void* d_out, int out_size) {
    const float* pos = (const float*)d_in[0];
    const float* sx  = (const float*)d_in[1];
    const float* sy  = (const float*)d_in[2];
    const float* ax  = (const float*)d_in[3];
    const float* bx  = (const float*)d_in[4];
    const float* cx  = (const float*)d_in[5];
    const float* ay  = (const float*)d_in[6];
    const float* by  = (const float*)d_in[7];
    const float* cy  = (const float*)d_in[8];
    // d_in[9], d_in[10]: bin_center_x/y (computed analytically instead)
    const float* initial = (const float*)d_in[11];
    float* out = (float*)d_out;

    int n = in_sizes[1];  // number of nodes (pos is 2N)

    init_kernel<<<(NBX * NBY + 255) / 256, 256>>>(initial, out);
    scatter_kernel<<<(n + 255) / 256, 256>>>(pos, sx, sy, ax, bx, cx, ay, by, cy, n);
    reduce_kernel<<<256, 256>>>(out);
}

// round 2
// speedup vs baseline: 2.5625x; 2.5625x over previous
#include <cuda_runtime.h>
#include <cuda_bf16.h>

#define NBX 512
#define NBY 512
#define KK  5
#define BINF 1.0f
#define TARGET_AREA 0.9f   // TARGET_DENSITY * BIN * BIN

// Scratch density map (device global; no cudaMalloc allowed)
__device__ __align__(16) float g_density[NBX * NBY];

// ---------------------------------------------------------------------------
// Kernel 1: init density map from initial_density_map, zero the output scalar
// ---------------------------------------------------------------------------
__global__ void init_kernel(const float* __restrict__ initial, float* __restrict__ out) {
    int i = blockIdx.x * blockDim.x + threadIdx.x;
    if (i < NBX * NBY) g_density[i] = initial[i];
    if (i == 0) out[0] = 0.0f;
}

// Vectorized fp32 reduction (no return) — sm_90+
__device__ __forceinline__ void red_add_v4(float* addr, float a, float b, float c, float d) {
    asm volatile("red.global.add.v4.f32 [%0], {%1, %2, %3, %4};"
                 :: "l"(addr), "f"(a), "f"(b), "f"(c), "f"(d) : "memory");
}

// ---------------------------------------------------------------------------
// Kernel 2: per-node 5x5 separable bell-potential scatter, float4 REDs
// ---------------------------------------------------------------------------
__global__ void __launch_bounds__(256) scatter_kernel(
    const float* __restrict__ pos,   // [2N]: x then y
    const float* __restrict__ sxs,
    const float* __restrict__ sys,
    const float* __restrict__ axs,
    const float* __restrict__ bxs,
    const float* __restrict__ cxs,
    const float* __restrict__ ays,
    const float* __restrict__ bys,
    const float* __restrict__ cys,
    int n)
{
    int i = blockIdx.x * blockDim.x + threadIdx.x;
    if (i >= n) return;

    float x  = pos[i];
    float y  = pos[n + i];
    float sx = sxs[i];
    float sy = sys[i];
    float ax = axs[i], bx = bxs[i], cx = cxs[i];
    float ay = ays[i], by = bys[i], cy = cys[i];

    // ----- x axis: 5 row potentials -----
    float cxr = x + 0.5f * sx;                 // node center
    int sx0 = (int)floorf(x - 2.0f * BINF);    // XL=0, BIN=1
    sx0 = min(max(sx0, 0), NBX - KK);
    float p1x = 0.5f * sx + BINF;
    float p2x = 0.5f * sx + 2.0f * BINF;
    float cbx = cx * bx;

    float px[KK];
#pragma unroll
    for (int k = 0; k < KK; k++) {
        float bc = ((float)(sx0 + k) + 0.5f) * BINF;
        float d  = fabsf(cxr - bc);
        float pot;
        if (d < p1x) {
            pot = cx * (1.0f - ax * d * d);
        } else if (d < p2x) {
            float t = d - p2x;
            pot = cbx * t * t;
        } else {
            pot = 0.0f;
        }
        px[k] = pot;
    }

    // ----- y axis: 8 padded/aligned potentials (window-masked) -----
    float cyr = y + 0.5f * sy;
    int sy0 = (int)floorf(y - 2.0f * BINF);
    sy0 = min(max(sy0, 0), NBY - KK);
    int ybase = sy0 & ~3;                      // 16B-aligned column base
    float p1y = 0.5f * sy + BINF;
    float p2y = 0.5f * sy + 2.0f * BINF;
    float cby = cy * by;

    float pyp[8];
#pragma unroll
    for (int j = 0; j < 8; j++) {
        int g = ybase + j;
        float bc = ((float)g + 0.5f) * BINF;
        float d  = fabsf(cyr - bc);
        float pot;
        if (d < p1y) {
            pot = cy * (1.0f - ay * d * d);
        } else if (d < p2y) {
            float t = d - p2y;
            pot = cby * t * t;
        } else {
            pot = 0.0f;
        }
        // deposit only into the reference's 5-bin window
        bool in = (g >= sy0) && (g < sy0 + KK);
        pyp[j] = in ? pot : 0.0f;
    }

    // ----- 5 rows x 2 float4 vector reductions -----
    float* base = &g_density[sx0 * NBY + ybase];
#pragma unroll
    for (int kx = 0; kx < KK; kx++) {
        float vx = px[kx];
        if (vx != 0.0f) {
            float q0 = vx * pyp[0], q1 = vx * pyp[1], q2 = vx * pyp[2], q3 = vx * pyp[3];
            float q4 = vx * pyp[4], q5 = vx * pyp[5], q6 = vx * pyp[6], q7 = vx * pyp[7];
            if (q0 != 0.0f || q1 != 0.0f || q2 != 0.0f || q3 != 0.0f)
                red_add_v4(base, q0, q1, q2, q3);
            if (q4 != 0.0f || q5 != 0.0f || q6 != 0.0f || q7 != 0.0f)
                red_add_v4(base + 4, q4, q5, q6, q7);
        }
        base += NBY;
    }
}

// ---------------------------------------------------------------------------
// Kernel 3: cost = sum((density - target)^2)
// ---------------------------------------------------------------------------
__global__ void __launch_bounds__(256) reduce_kernel(float* __restrict__ out) {
    __shared__ float sdata[8];
    int tid = threadIdx.x;
    float acc = 0.0f;
    for (int i = blockIdx.x * blockDim.x + tid; i < NBX * NBY;
         i += gridDim.x * blockDim.x) {
        float d = g_density[i] - TARGET_AREA;
        acc += d * d;
    }
#pragma unroll
    for (int off = 16; off > 0; off >>= 1)
        acc += __shfl_xor_sync(0xFFFFFFFF, acc, off);
    if ((tid & 31) == 0) sdata[tid >> 5] = acc;
    __syncthreads();
    if (tid < 8) {
        float v = sdata[tid];
#pragma unroll
        for (int off = 4; off > 0; off >>= 1)
            v += __shfl_xor_sync(0xFF, v, off);
        if (tid == 0) atomicAdd(out, v);
    }
}

// ---------------------------------------------------------------------------
extern "C" void kernel_launch(void* const* d_in, const int* in_sizes, int n_in,
                              void* d_out, int out_size) {
    const float* pos = (const float*)d_in[0];
    const float* sx  = (const float*)d_in[1];
    const float* sy  = (const float*)d_in[2];
    const float* ax  = (const float*)d_in[3];
    const float* bx  = (const float*)d_in[4];
    const float* cx  = (const float*)d_in[5];
    const float* ay  = (const float*)d_in[6];
    const float* by  = (const float*)d_in[7];
    const float* cy  = (const float*)d_in[8];
    // d_in[9], d_in[10]: bin_center_x/y (computed analytically instead)
    const float* initial = (const float*)d_in[11];
    float* out = (float*)d_out;

    int n = in_sizes[1];  // number of nodes (pos is 2N)

    init_kernel<<<(NBX * NBY + 255) / 256, 256>>>(initial, out);
    scatter_kernel<<<(n + 255) / 256, 256>>>(pos, sx, sy, ax, bx, cx, ay, by, cy, n);
    reduce_kernel<<<256, 256>>>(out);
}